// round 8
// baseline (speedup 1.0000x reference)
#include <cuda_runtime.h>

// ---------------- problem constants ----------------
#define BB 64
#define SS 129
#define FF 768
#define DD 4
#define KDIM (SS*FF)        // 99072
#define N3 (3*BB)           // 192
#define MOM 0.9f
#define EPSV 1e-6f

// output layout (tuple flattened)
#define XMIX_N (BB*SS*FF)
#define LOSS_OFF XMIX_N
#define NM_OFF (XMIX_N + 1)
#define NV_OFF (NM_OFF + DD*FF)

// ---------------- gram config ----------------
#define KSPLIT 144          // CTAs (144 of 148 SMs busy)
#define TOTTILES 3096       // KDIM / 32
#define SROW 36
#define BUF_ELEMS (N3*SROW)
#define NPAIR 6
#define PAIRSZ 4096
#define KSLAB (NPAIR*PAIRSZ)   // 24576
#define GTHREADS 768

// ---------------- device scratch ----------------
__device__ float g_pA1[4][BB*FF];
__device__ float g_pA2[4][BB*FF];
__device__ float g_mu[BB*FF];
__device__ float g_inv[BB*FF];
__device__ float g_nm[DD*FF];
__device__ float g_nsd[DD*FF];
__device__ float g_gpart[KSPLIT*KSLAB];
__device__ float g_part2[8][KSLAB];
__device__ float g_G[N3*N3];
__device__ float g_rowloss[N3];

// ---------------- helpers ----------------
__device__ __forceinline__ unsigned tf32r(float v) {
    unsigned r;
    asm("cvt.rna.tf32.f32 %0, %1;" : "=r"(r) : "f"(v));
    return r;
}

__device__ __forceinline__ void mma_tf32(float* d, const unsigned* a, const unsigned* b) {
    asm volatile("mma.sync.aligned.m16n8k8.row.col.f32.tf32.tf32.f32 "
        "{%0,%1,%2,%3},{%4,%5,%6,%7},{%8,%9},{%0,%1,%2,%3};"
        : "+f"(d[0]), "+f"(d[1]), "+f"(d[2]), "+f"(d[3])
        : "r"(a[0]), "r"(a[1]), "r"(a[2]), "r"(a[3]), "r"(b[0]), "r"(b[1]));
}

// ---------------- stage A1: split-S partial sums -----------------------------
__global__ void stageA1(const float* __restrict__ x) {
    int bf = blockIdx.x;
    int seg = blockIdx.y;
    int b = bf / 3;
    int f = (bf % 3) * 256 + threadIdx.x;
    int s0 = (seg == 0) ? 0 : 33 + 32 * (seg - 1);
    int s1 = 33 + 32 * seg;
    const float* p = x + (size_t)b * KDIM + f;
    float sa = 0.f, sb2 = 0.f, sc = 0.f, sd2 = 0.f;
    int ss = s0;
    for (; ss + 1 < s1; ss += 2) {
        float v0 = p[(size_t)ss * FF];
        float v1 = p[(size_t)(ss + 1) * FF];
        sa += v0; sb2 += v0 * v0;
        sc += v1; sd2 += v1 * v1;
    }
    if (ss < s1) { float v = p[(size_t)ss * FF]; sa += v; sb2 += v * v; }
    int o = b * FF + f;
    g_pA1[seg][o] = sa + sc;
    g_pA2[seg][o] = sb2 + sd2;
}

// ------- stage AB: combine partials + instance stats + domain EMA ------------
__global__ void stageAB(const float* __restrict__ mean_buf,
                        const float* __restrict__ var_buf,
                        const int* __restrict__ domain,
                        float* __restrict__ out) {
    __shared__ float s1s[64][65];
    __shared__ float s2s[64][65];
    __shared__ int doms[64];
    int tid = threadIdx.x;
    int f0 = blockIdx.x * 64;
    if (tid < 64) doms[tid] = domain[tid];
    #pragma unroll
    for (int i = 0; i < 16; i++) {
        int e = tid + 256 * i;
        int b = e >> 6, f = e & 63;
        int idx = b * FF + f0 + f;
        float s  = g_pA1[0][idx] + g_pA1[1][idx] + g_pA1[2][idx] + g_pA1[3][idx];
        float s2 = g_pA2[0][idx] + g_pA2[1][idx] + g_pA2[2][idx] + g_pA2[3][idx];
        float mu = s / (float)SS;
        float var = (s2 - (float)SS * mu * mu) / (float)(SS - 1);
        g_mu[idx] = mu;
        g_inv[idx] = rsqrtf(var + EPSV);
        s1s[b][f] = s;
        s2s[b][f] = s2;
    }
    __syncthreads();
    int d = tid >> 6, f = tid & 63;
    float s1 = 0.f, s2 = 0.f;
    int nb = 0;
    #pragma unroll 8
    for (int b = 0; b < BB; b++) {
        if (doms[b] == d) {
            nb++;
            s1 += s1s[b][f];
            s2 += s2s[b][f];
        }
    }
    float n = (float)nb * (float)SS;
    float mu = s1 / fmaxf(n, 1.f);
    float var = (s2 - n * mu * mu) / fmaxf(n - 1.f, 1.f);
    int idx = d * FF + f0 + f;
    float nm, nv;
    if (nb > 0) {
        nm = MOM * mean_buf[idx] + (1.f - MOM) * mu;
        nv = MOM * var_buf[idx] + (1.f - MOM) * var;
    } else {
        nm = mean_buf[idx];
        nv = var_buf[idx];
    }
    out[NM_OFF + idx] = nm;
    out[NV_OFF + idx] = nv;
    g_nm[idx] = nm;
    g_nsd[idx] = sqrtf(nv + EPSV);
}

// ---------------- fused gram (tf32 mma.sync) + xmix + hg ---------------------
// 768 threads. Loader: 2 units/thread over 1536 row-quads. MMA: 6 warp groups
// of 4 warps; group g computes pair-tile g (2x2 warp grid, 32 acc regs/thread).
__global__ __launch_bounds__(GTHREADS, 1)
void gram_tc(const float* __restrict__ x,
             const float* __restrict__ hgn,
             const float* __restrict__ lmda,
             const int* __restrict__ domain,
             const int* __restrict__ drand,
             float* __restrict__ out) {
    extern __shared__ unsigned sbuf[];   // 2 * BUF_ELEMS
    int tid = threadIdx.x;
    int ks = blockIdx.x;
    int start = ks * 21 + min(ks, 72);            // first tile index
    int ntile = 21 + (ks < 72 ? 1 : 0);
    long kbase = (long)start * 32;

    // ---- loader units: e0 = tid (rows 0..95), e1 = tid+768 (rows 96..191) ----
    // mode 0: raw x row | mode 1: xmix row (reads x, writes out) | mode 2: hg
    const float* srcp[2];
    int soff[2], mode[2];
    int offm = 0, offdx = 0, offdh[2] = {0, 0};
    float lm = 0.f;
    float* outp = 0;
    #pragma unroll
    for (int u = 0; u < 2; u++) {
        int e = tid + 768 * u;
        int row = e >> 3, q = e & 7;
        soff[u] = row * SROW + q * 4;
        if (row < 64) {
            mode[u] = 0;
            srcp[u] = x + (size_t)row * KDIM + kbase + q * 4;
        } else if (row < 128) {
            mode[u] = 1;
            int b = row - 64;
            srcp[u] = x + (size_t)b * KDIM + kbase + q * 4;
            outp = out + (size_t)b * KDIM + kbase + q * 4;
            lm = lmda[b];
            int dom = domain[b];
            int ds = (dom + drand[b]) & 3;
            offm  = b * FF + q * 4;
            offdx = ds * FF + q * 4;
        } else {
            mode[u] = 2;
            int b = row - 128;
            srcp[u] = hgn + (size_t)b * KDIM + kbase + q * 4;
            offdh[u] = domain[b] * FF + q * 4;
        }
    }

    // ---- mma setup ----
    int wid = tid >> 5, lane = tid & 31;
    int grp = wid >> 2, wq = wid & 3;
    int wm = wq >> 1, wn = wq & 1;
    int lr = lane >> 2, lc = lane & 3;
    const int TIa[NPAIR] = {0,0,0,1,1,2};
    const int TJa[NPAIR] = {0,1,2,1,2,2};
    int ti = TIa[grp], tj = TJa[grp];
    float acc[2][4][4];
    #pragma unroll
    for (int mt = 0; mt < 2; mt++)
        #pragma unroll
        for (int nt = 0; nt < 4; nt++)
            #pragma unroll
            for (int r = 0; r < 4; r++) acc[mt][nt][r] = 0.f;

    float4 v0 = *(const float4*)srcp[0];
    float4 v1 = *(const float4*)srcp[1];
    int fm = start % 24;                 // f-tile phase (f = fm*32 + q*4)

    for (int t = 0; t < ntile; t++) {
        unsigned* bb = sbuf + (t & 1) * BUF_ELEMS;
        int fo = fm * 32;
        fm = (fm + 1 == 24) ? 0 : fm + 1;
        float4 w0 = v0, w1 = v1;
        // unit transforms
        #pragma unroll
        for (int u = 0; u < 2; u++) {
            float4& w = u ? w1 : w0;
            if (mode[u] == 1) {
                float4 mu = *(const float4*)(g_mu  + offm  + fo);
                float4 iv = *(const float4*)(g_inv + offm  + fo);
                float4 nm = *(const float4*)(g_nm  + offdx + fo);
                float4 sd = *(const float4*)(g_nsd + offdx + fo);
                float il = 1.f - lm;
                float4 xm;
                xm.x = lm * w.x + il * fmaf((w.x - mu.x) * iv.x, sd.x, nm.x);
                xm.y = lm * w.y + il * fmaf((w.y - mu.y) * iv.y, sd.y, nm.y);
                xm.z = lm * w.z + il * fmaf((w.z - mu.z) * iv.z, sd.z, nm.z);
                xm.w = lm * w.w + il * fmaf((w.w - mu.w) * iv.w, sd.w, nm.w);
                *(float4*)(outp + t * 32) = xm;
                w = xm;
            } else if (mode[u] == 2) {
                float4 nm = *(const float4*)(g_nm  + offdh[u] + fo);
                float4 sd = *(const float4*)(g_nsd + offdh[u] + fo);
                w.x = fmaf(sd.x, w.x, nm.x);
                w.y = fmaf(sd.y, w.y, nm.y);
                w.z = fmaf(sd.z, w.z, nm.z);
                w.w = fmaf(sd.w, w.w, nm.w);
            }
        }
        uint4 u0, u1;
        u0.x = tf32r(w0.x); u0.y = tf32r(w0.y); u0.z = tf32r(w0.z); u0.w = tf32r(w0.w);
        u1.x = tf32r(w1.x); u1.y = tf32r(w1.y); u1.z = tf32r(w1.z); u1.w = tf32r(w1.w);
        *(uint4*)(&bb[soff[0]]) = u0;
        *(uint4*)(&bb[soff[1]]) = u1;
        if (t + 1 < ntile) {
            v0 = *(const float4*)(srcp[0] + (t + 1) * 32);
            v1 = *(const float4*)(srcp[1] + (t + 1) * 32);
        }
        __syncthreads();
        const unsigned* S = bb;
        #pragma unroll
        for (int kk = 0; kk < 4; kk++) {
            int k0 = kk * 8;
            unsigned af[2][4], bfr[4][2];
            #pragma unroll
            for (int mt = 0; mt < 2; mt++) {
                int r0 = ti * 64 + wm * 32 + mt * 16 + lr;
                af[mt][0] = S[r0 * SROW + k0 + lc];
                af[mt][1] = S[(r0 + 8) * SROW + k0 + lc];
                af[mt][2] = S[r0 * SROW + k0 + lc + 4];
                af[mt][3] = S[(r0 + 8) * SROW + k0 + lc + 4];
            }
            #pragma unroll
            for (int nt = 0; nt < 4; nt++) {
                int n0 = tj * 64 + wn * 32 + nt * 8 + lr;
                bfr[nt][0] = S[n0 * SROW + k0 + lc];
                bfr[nt][1] = S[n0 * SROW + k0 + lc + 4];
            }
            #pragma unroll
            for (int mt = 0; mt < 2; mt++)
                #pragma unroll
                for (int nt = 0; nt < 4; nt++)
                    mma_tf32(acc[mt][nt], af[mt], bfr[nt]);
        }
        __syncthreads();
    }

    // ---- epilogue: each group writes its pair-tile ----
    float* base = g_gpart + (size_t)ks * KSLAB + grp * PAIRSZ;
    #pragma unroll
    for (int mt = 0; mt < 2; mt++) {
        #pragma unroll
        for (int nt = 0; nt < 4; nt++) {
            int r = wm * 32 + mt * 16 + lr;
            int c = wn * 32 + nt * 8 + lc * 2;
            float* dst = base + r * 64 + c;
            *(float2*)dst = make_float2(acc[mt][nt][0], acc[mt][nt][1]);
            *(float2*)(dst + 8 * 64) = make_float2(acc[mt][nt][2], acc[mt][nt][3]);
        }
    }
}

// ---------------- split-K reduction stage 1: 144 -> 8 (float4) ---------------
__global__ void reduceG1() {
    int i4 = (blockIdx.x * 256 + threadIdx.x) * 4;   // 24 blocks -> 24576 floats
    int c = blockIdx.y;                               // 0..7, 18 partials each
    const float* src = g_gpart + (size_t)(c * 18) * KSLAB + i4;
    float4 a0 = make_float4(0.f, 0.f, 0.f, 0.f);
    float4 a1 = a0, a2 = a0;
    #pragma unroll
    for (int p = 0; p < 18; p += 3) {
        float4 v0 = *(const float4*)(src + (size_t)p * KSLAB);
        float4 v1 = *(const float4*)(src + (size_t)(p + 1) * KSLAB);
        float4 v2 = *(const float4*)(src + (size_t)(p + 2) * KSLAB);
        a0.x += v0.x; a0.y += v0.y; a0.z += v0.z; a0.w += v0.w;
        a1.x += v1.x; a1.y += v1.y; a1.z += v1.z; a1.w += v1.w;
        a2.x += v2.x; a2.y += v2.y; a2.z += v2.z; a2.w += v2.w;
    }
    float4 r;
    r.x = a0.x + a1.x + a2.x;
    r.y = a0.y + a1.y + a2.y;
    r.z = a0.z + a1.z + a2.z;
    r.w = a0.w + a1.w + a2.w;
    *(float4*)(&g_part2[c][i4]) = r;
}

// ---------------- stage 2: sum 8 chunks + symmetry mirror --------------------
__global__ void reduceG2() {
    int idx = blockIdx.x * 256 + threadIdx.x;
    if (idx >= N3 * N3) return;
    int i = idx / N3, j = idx % N3;
    int ti = i >> 6, tj = j >> 6, li = i & 63, lj = j & 63;
    int a, b2, la, lb;
    if (ti <= tj) { a = ti; b2 = tj; la = li; lb = lj; }
    else          { a = tj; b2 = ti; la = lj; lb = li; }
    int pair = a * (5 - a) / 2 + b2;
    int o = pair * PAIRSZ + la * 64 + lb;
    float s = 0.f;
    #pragma unroll
    for (int c = 0; c < 8; c++) s += g_part2[c][o];
    g_G[idx] = s;
}

// ---------------- triplet loss: warp per row ---------------------------------
__global__ void lossA(const int* __restrict__ labels) {
    int i = (blockIdx.x * blockDim.x + threadIdx.x) >> 5;
    int lane = threadIdx.x & 31;
    int li = (i < 2 * BB) ? labels[i & 63] : -1;
    float sqi = g_G[i * N3 + i];
    float ap = -1e30f, an = 1e30f;
    #pragma unroll
    for (int jj = 0; jj < 6; jj++) {
        int j = lane + jj * 32;
        int lj = (j < 2 * BB) ? labels[j & 63] : -1;
        float d2 = sqi + g_G[j * N3 + j] - 2.f * g_G[i * N3 + j];
        float dd = sqrtf(fmaxf(d2, 1e-12f));
        if (li == lj) ap = fmaxf(ap, dd);
        else          an = fminf(an, dd);
    }
    #pragma unroll
    for (int o = 16; o > 0; o >>= 1) {
        ap = fmaxf(ap, __shfl_xor_sync(0xFFFFFFFFu, ap, o));
        an = fminf(an, __shfl_xor_sync(0xFFFFFFFFu, an, o));
    }
    if (lane == 0) {
        float z = ap - an;
        g_rowloss[i] = (z > 0.f) ? (z + log1pf(expf(-z))) : log1pf(expf(z));
    }
}

__global__ void lossB(float* __restrict__ out) {
    __shared__ float red[256];
    int t = threadIdx.x;
    red[t] = (t < N3) ? g_rowloss[t] : 0.f;
    __syncthreads();
    for (int st = 128; st > 0; st >>= 1) {
        if (t < st) red[t] += red[t + st];
        __syncthreads();
    }
    if (t == 0) out[LOSS_OFF] = red[0] / (float)N3;
}

// ---------------- launch ------------------------------------------------------
extern "C" void kernel_launch(void* const* d_in, const int* in_sizes, int n_in,
                              void* d_out, int out_size) {
    const float* x        = (const float*)d_in[0];
    const float* lmda     = (const float*)d_in[1];
    const float* mean_buf = (const float*)d_in[2];
    const float* var_buf  = (const float*)d_in[3];
    const float* hgn      = (const float*)d_in[4];
    const int*   labels   = (const int*)d_in[5];
    const int*   domain   = (const int*)d_in[6];
    const int*   d_rand   = (const int*)d_in[7];
    float* out = (float*)d_out;

    int smem_sz = 2 * BUF_ELEMS * (int)sizeof(unsigned);   // 55296
    cudaFuncSetAttribute(gram_tc, cudaFuncAttributeMaxDynamicSharedMemorySize, smem_sz);

    dim3 ga(BB * 3, 4);
    stageA1<<<ga, 256>>>(x);
    stageAB<<<FF / 64, 256>>>(mean_buf, var_buf, domain, out);
    gram_tc<<<KSPLIT, GTHREADS, smem_sz>>>(x, hgn, lmda, domain, d_rand, out);
    dim3 gr(KSLAB / 1024, 8);
    reduceG1<<<gr, 256>>>();
    reduceG2<<<(N3 * N3 + 255) / 256, 256>>>();
    lossA<<<N3 / 8, 256>>>(labels);
    lossB<<<1, 256>>>(out);
}